// round 8
// baseline (speedup 1.0000x reference)
#include <cuda_runtime.h>

#define B_ 256
#define S_ 197
#define D_ 768
#define D4_ 192
#define P_ 20
#define L_ 5
#define T_ 10
#define K_ 5
#define ROWS_TOK 75            // (T+K)*L
#define ROWS_ASSIST 50         // T*L
#define ROWS_PE 272            // ROWS_TOK + S
#define Q_ 8                   // mean/copy chunks per batch row
#define CHUNK 25               // rows per chunk (last chunk = 22)
#define TGRP 15                // token rows per fused-kernel block
#define NTG 5                  // token groups (5*15 = 75)
#define RSB 16                 // reduce_sim blocks (16 b's each)

// float offsets into d_out
#define PE_OFF   0ULL
#define SIM_OFF  53477376ULL
#define TOK_OFF  53477377ULL
#define IDX_OFF  68222977ULL
#define XN_OFF   68224257ULL

// scratch (device globals; no allocations)
__device__ float g_part[Q_ * B_ * D_];
__device__ float g_xnorm[B_ * D_];
__device__ float g_pnorm[P_ * D_];
__device__ int   g_idx[B_ * K_];
__device__ int   g_cnt[P_];
__device__ volatile int g_flag[B_];

// 192-thread block reduce (padded to 256 in shared)
__device__ __forceinline__ float blk_reduce_192(float v) {
    __shared__ float sh[256];
    int t = threadIdx.x;
    sh[t] = v;
    if (t < 64) sh[192 + t] = 0.f;
    __syncthreads();
    for (int s = 128; s > 0; s >>= 1) {
        if (t < s) sh[t] += sh[t + s];
        __syncthreads();
    }
    return sh[0];
}

// ---------------------------------------------------------------------------
// Kernel 1: grid (B, Q_+1), block 192.
//  q<Q_ : stream x_embed rows chunk -> prompted_embedding[:, 75:, :] + partials.
//  q==Q_: zero flag[b]; b<P -> l2-normalize prompt_key row b; b==0 zero cnt+SIM.
// ---------------------------------------------------------------------------
__global__ void k_mean_copy(const float4* __restrict__ x,
                            const float4* __restrict__ pk,
                            float* __restrict__ out) {
    int b = blockIdx.x;
    int q = blockIdx.y;
    int t = threadIdx.x;                 // 0..191

    if (q == Q_) {
        if (t == 0) g_flag[b] = 0;
        if (b == 0 && t < P_) g_cnt[t] = 0;
        if (b == 0 && t == 0) out[SIM_OFF] = 0.f;
        if (b >= P_) return;
        float4 v = pk[(size_t)b * D4_ + t];
        float ss = blk_reduce_192(v.x * v.x + v.y * v.y + v.z * v.z + v.w * v.w);
        float r = rsqrtf(fmaxf(ss, 1e-12f));
        float4 n = make_float4(v.x * r, v.y * r, v.z * r, v.w * r);
        ((float4*)g_pnorm)[(size_t)b * D4_ + t] = n;
        return;
    }

    int s0 = q * CHUNK;
    int s1 = (q == Q_ - 1) ? S_ : s0 + CHUNK;

    const float4* xb = x + (size_t)b * S_ * D4_ + t;
    float4* ob = ((float4*)(out + PE_OFF)) + (size_t)b * ROWS_PE * D4_ + (size_t)ROWS_TOK * D4_ + t;

    float4 acc = make_float4(0.f, 0.f, 0.f, 0.f);
    int s = s0;
    for (; s + 5 <= s1; s += 5) {
        float4 v0 = __ldcs(xb + (size_t)(s + 0) * D4_);
        float4 v1 = __ldcs(xb + (size_t)(s + 1) * D4_);
        float4 v2 = __ldcs(xb + (size_t)(s + 2) * D4_);
        float4 v3 = __ldcs(xb + (size_t)(s + 3) * D4_);
        float4 v4 = __ldcs(xb + (size_t)(s + 4) * D4_);
        acc.x += v0.x + v1.x + v2.x + v3.x + v4.x;
        acc.y += v0.y + v1.y + v2.y + v3.y + v4.y;
        acc.z += v0.z + v1.z + v2.z + v3.z + v4.z;
        acc.w += v0.w + v1.w + v2.w + v3.w + v4.w;
        __stcs(ob + (size_t)(s + 0) * D4_, v0);
        __stcs(ob + (size_t)(s + 1) * D4_, v1);
        __stcs(ob + (size_t)(s + 2) * D4_, v2);
        __stcs(ob + (size_t)(s + 3) * D4_, v3);
        __stcs(ob + (size_t)(s + 4) * D4_, v4);
    }
    for (; s < s1; s++) {
        float4 v = __ldcs(xb + (size_t)s * D4_);
        acc.x += v.x; acc.y += v.y; acc.z += v.z; acc.w += v.w;
        __stcs(ob + (size_t)s * D4_, v);
    }
    ((float4*)g_part)[(size_t)q * B_ * D4_ + (size_t)b * D4_ + t] = acc;
}

// write TGRP token rows [rbase, rbase+15) for batch b (row source resolved)
__device__ __forceinline__ void write_rows(int rbase, int b, int t,
                                           const float4* __restrict__ prompt,
                                           const float4* __restrict__ assist,
                                           float* __restrict__ out,
                                           const int* idxrow) {
    float4* pe = (float4*)(out + PE_OFF) + (size_t)b * ROWS_PE * D4_ + t;
    float* tokbase = out + TOK_OFF + (size_t)b * ROWS_TOK * D_ + (size_t)t * 4;
#pragma unroll
    for (int batch = 0; batch < 3; batch++) {
        int r0 = rbase + batch * 5;
        float4 v[5];
#pragma unroll
        for (int i = 0; i < 5; i++) {
            int r = r0 + i;
            if (r < ROWS_ASSIST) {
                v[i] = assist[(size_t)r * D4_ + t];
            } else {
                int rr = r - ROWS_ASSIST;
                int idx = idxrow[rr / L_];
                v[i] = make_float4(0.f, 0.f, 0.f, 0.f);
                if (idx >= 0)
                    v[i] = prompt[((size_t)idx * L_ + (rr % L_)) * D4_ + t];
            }
        }
#pragma unroll
        for (int i = 0; i < 5; i++)
            __stcs(pe + (size_t)(r0 + i) * D4_, v[i]);
#pragma unroll
        for (int i = 0; i < 5; i++) {
            float* to = tokbase + (size_t)(r0 + i) * D_;
            __stcs(to + 0, v[i].x);
            __stcs(to + 1, v[i].y);
            __stcs(to + 2, v[i].z);
            __stcs(to + 3, v[i].w);
        }
    }
}

// ---------------------------------------------------------------------------
// Kernel 2 (fused): grid (NTG, B), block 192. 1280 blocks — all co-resident.
//  g==0 : partials -> mean -> l2norm -> x_norm out; 20 dots; top-5; publish
//         g_idx[b] + flag; then write rows 0-14 (assist).
//  g=1,2: rows 15-44 (assist; no dependency).
//  g=3,4: assist part first (45-49), spin on flag[b], then selected rows.
// ---------------------------------------------------------------------------
__global__ void k_fused(const float4* __restrict__ prompt,
                        const float4* __restrict__ assist,
                        float* __restrict__ out) {
    int g = blockIdx.x;      // 0..4
    int b = blockIdx.y;
    int t = threadIdx.x;     // 0..191
    __shared__ int shidx[K_];

    if (g == 0) {
        __shared__ float  sh[256];
        __shared__ float4 shx[D4_];
        __shared__ float  shsim[P_];

        const float4* part = (const float4*)g_part + (size_t)b * D4_ + t;
        float4 a = make_float4(0.f, 0.f, 0.f, 0.f);
#pragma unroll
        for (int q = 0; q < Q_; q++) {
            float4 c = part[(size_t)q * B_ * D4_];
            a.x += c.x; a.y += c.y; a.z += c.z; a.w += c.w;
        }
        const float inv = 1.0f / (float)S_;
        a.x *= inv; a.y *= inv; a.z *= inv; a.w *= inv;

        sh[t] = a.x * a.x + a.y * a.y + a.z * a.z + a.w * a.w;
        if (t < 64) sh[192 + t] = 0.f;
        __syncthreads();
        for (int s = 128; s > 0; s >>= 1) {
            if (t < s) sh[t] += sh[t + s];
            __syncthreads();
        }
        float r = rsqrtf(fmaxf(sh[0], 1e-12f));
        float4 n = make_float4(a.x * r, a.y * r, a.z * r, a.w * r);

        ((float4*)g_xnorm)[(size_t)b * D4_ + t] = n;
        float* xo = out + XN_OFF + (size_t)b * D_ + (size_t)t * 4;
        xo[0] = n.x; xo[1] = n.y; xo[2] = n.z; xo[3] = n.w;

        shx[t] = n;
        __syncthreads();

        int w = t >> 5;
        int lane = t & 31;
        for (int p = w; p < P_; p += 6) {
            const float4* pn = ((const float4*)g_pnorm) + (size_t)p * D4_;
            float acc = 0.f;
#pragma unroll
            for (int i = 0; i < 6; i++) {
                int j = lane + 32 * i;
                float4 pv = pn[j];
                float4 xv = shx[j];
                acc += xv.x * pv.x + xv.y * pv.y + xv.z * pv.z + xv.w * pv.w;
            }
#pragma unroll
            for (int off = 16; off > 0; off >>= 1)
                acc += __shfl_down_sync(0xffffffffu, acc, off);
            if (lane == 0) shsim[p] = acc;
        }
        __syncthreads();

        if (t == 0) {
            float sim[P_];
            bool used[P_];
#pragma unroll
            for (int p = 0; p < P_; p++) { sim[p] = shsim[p]; used[p] = false; }
            for (int k = 0; k < K_; k++) {
                float best = -3.4e38f;
                int bi = 0;
#pragma unroll
                for (int p = 0; p < P_; p++) {
                    if (!used[p] && sim[p] > best) { best = sim[p]; bi = p; }
                }
                used[bi] = true;
                bool keep = best > 0.0f;
                int idxp = keep ? bi : -1;
                g_idx[b * K_ + k] = idxp;
                shidx[k] = idxp;
                out[IDX_OFF + (size_t)b * K_ + k] = (float)idxp;
                if (keep) atomicAdd(&g_cnt[bi], 1);
            }
            __threadfence();
            g_flag[b] = 1;
        }
        __syncthreads();
        write_rows(0, b, t, prompt, assist, out, shidx);
        return;
    }

    if (g <= 2) {
        // pure assist rows: no dependency
        write_rows(g * TGRP, b, t, prompt, assist, out, shidx /*unused*/);
        return;
    }

    // g == 3 or 4: rows 45-59 / 60-74 — selected rows need g_idx[b]
    if (g == 3) {
        // assist rows 45-49 first (no dependency)
        float4* pe = (float4*)(out + PE_OFF) + (size_t)b * ROWS_PE * D4_ + t;
        float* tokbase = out + TOK_OFF + (size_t)b * ROWS_TOK * D_ + (size_t)t * 4;
        float4 v[5];
#pragma unroll
        for (int i = 0; i < 5; i++)
            v[i] = assist[(size_t)(45 + i) * D4_ + t];
#pragma unroll
        for (int i = 0; i < 5; i++)
            __stcs(pe + (size_t)(45 + i) * D4_, v[i]);
#pragma unroll
        for (int i = 0; i < 5; i++) {
            float* to = tokbase + (size_t)(45 + i) * D_;
            __stcs(to + 0, v[i].x);
            __stcs(to + 1, v[i].y);
            __stcs(to + 2, v[i].z);
            __stcs(to + 3, v[i].w);
        }
    }

    // wait for this b's topk
    if (t == 0) {
        while (g_flag[b] == 0) { __nanosleep(64); }
    }
    __syncthreads();
    __threadfence();
    if (t < K_) shidx[t] = g_idx[b * K_ + t];
    __syncthreads();

    int rbase = (g == 3) ? 50 : 60;
    int nrows = (g == 3) ? 10 : 15;
    float4* pe = (float4*)(out + PE_OFF) + (size_t)b * ROWS_PE * D4_ + t;
    float* tokbase = out + TOK_OFF + (size_t)b * ROWS_TOK * D_ + (size_t)t * 4;
    for (int r0 = rbase; r0 < rbase + nrows; r0 += 5) {
        float4 v[5];
#pragma unroll
        for (int i = 0; i < 5; i++) {
            int rr = r0 + i - ROWS_ASSIST;
            int idx = shidx[rr / L_];
            v[i] = make_float4(0.f, 0.f, 0.f, 0.f);
            if (idx >= 0)
                v[i] = prompt[((size_t)idx * L_ + (rr % L_)) * D4_ + t];
        }
#pragma unroll
        for (int i = 0; i < 5; i++)
            __stcs(pe + (size_t)(r0 + i) * D4_, v[i]);
#pragma unroll
        for (int i = 0; i < 5; i++) {
            float* to = tokbase + (size_t)(r0 + i) * D_;
            __stcs(to + 0, v[i].x);
            __stcs(to + 1, v[i].y);
            __stcs(to + 2, v[i].z);
            __stcs(to + 3, v[i].w);
        }
    }
}

// ---------------------------------------------------------------------------
// Kernel 3: reduce_sim. grid RSB, block 192.
// ---------------------------------------------------------------------------
__global__ void k_reducesim(float* __restrict__ out) {
    int b = blockIdx.x;   // 0..15
    int t = threadIdx.x;
    const float4* xn = (const float4*)g_xnorm + (size_t)(b * 16) * D4_ + t;
    float4 sx = make_float4(0.f, 0.f, 0.f, 0.f);
#pragma unroll
    for (int i = 0; i < 16; i++) {
        float4 v = xn[(size_t)i * D4_];
        sx.x += v.x; sx.y += v.y; sx.z += v.z; sx.w += v.w;
    }
    float4 kt = make_float4(0.f, 0.f, 0.f, 0.f);
#pragma unroll
    for (int p = 0; p < P_; p++) {
        float c = (float)g_cnt[p];
        float4 v = ((const float4*)g_pnorm)[(size_t)p * D4_ + t];
        kt.x += c * v.x; kt.y += c * v.y; kt.z += c * v.z; kt.w += c * v.w;
    }
    float partial = sx.x * kt.x + sx.y * kt.y + sx.z * kt.z + sx.w * kt.w;
    float tot = blk_reduce_192(partial);
    if (t == 0) atomicAdd(out + SIM_OFF, tot * (1.0f / (float)B_));
}

extern "C" void kernel_launch(void* const* d_in, const int* in_sizes, int n_in,
                              void* d_out, int out_size) {
    const float4* x_embed = (const float4*)d_in[0];        // [B,S,D]
    const float4* prompt = (const float4*)d_in[1];         // [P,L,D]
    const float4* prompt_key = (const float4*)d_in[2];     // [P,D]
    const float4* assist = (const float4*)d_in[3];         // [T,L,D]
    float* out = (float*)d_out;

    k_mean_copy<<<dim3(B_, Q_ + 1), D4_>>>(x_embed, prompt_key, out);
    k_fused<<<dim3(NTG, B_), D4_>>>(prompt, assist, out);
    k_reducesim<<<RSB, D4_>>>(out);
}

// round 9
// speedup vs baseline: 1.1564x; 1.1564x over previous
#include <cuda_runtime.h>

#define B_ 256
#define S_ 197
#define D_ 768
#define D4_ 192
#define P_ 20
#define L_ 5
#define T_ 10
#define K_ 5
#define ROWS_TOK 75            // (T+K)*L
#define ROWS_ASSIST 50         // T*L
#define ROWS_PE 272            // ROWS_TOK + S
#define Q_ 8                   // mean/copy chunks per batch row
#define CHUNK 25               // rows per chunk (last chunk = 22)
#define RSB 16                 // reduce_sim blocks (16 b's each)

// float offsets into d_out
#define PE_OFF   0ULL
#define SIM_OFF  53477376ULL
#define TOK_OFF  53477377ULL
#define IDX_OFF  68222977ULL
#define XN_OFF   68224257ULL

// scratch (device globals; no allocations)
__device__ float g_part[Q_ * B_ * D_];
__device__ float g_xnorm[B_ * D_];
__device__ float g_pnorm[P_ * D_];
__device__ int   g_idx[B_ * K_];
__device__ int   g_cnt[P_];

// 192-thread block reduce (padded to 256 in shared)
__device__ __forceinline__ float blk_reduce_192(float v) {
    __shared__ float sh[256];
    int t = threadIdx.x;
    sh[t] = v;
    if (t < 64) sh[192 + t] = 0.f;
    __syncthreads();
    for (int s = 128; s > 0; s >>= 1) {
        if (t < s) sh[t] += sh[t + s];
        __syncthreads();
    }
    return sh[0];
}

// ---------------------------------------------------------------------------
// Kernel 1: grid (B, Q_+1), block 192.
//  q<Q_ : stream x_embed rows chunk -> prompted_embedding[:, 75:, :] + partials.
//  q==Q_: b<P -> l2-normalize prompt_key row b; b==0 zeroes g_cnt + SIM slot.
// ---------------------------------------------------------------------------
__global__ void k_mean_copy(const float4* __restrict__ x,
                            const float4* __restrict__ pk,
                            float* __restrict__ out) {
    int b = blockIdx.x;
    int q = blockIdx.y;
    int t = threadIdx.x;                 // 0..191

    if (q == Q_) {
        if (b == 0 && t < P_) g_cnt[t] = 0;
        if (b == 0 && t == 0) out[SIM_OFF] = 0.f;
        if (b < P_) {
            float4 v = pk[(size_t)b * D4_ + t];
            float ss = blk_reduce_192(v.x * v.x + v.y * v.y + v.z * v.z + v.w * v.w);
            float r = rsqrtf(fmaxf(ss, 1e-12f));
            float4 n = make_float4(v.x * r, v.y * r, v.z * r, v.w * r);
            ((float4*)g_pnorm)[(size_t)b * D4_ + t] = n;
        }
        cudaTriggerProgrammaticLaunchCompletion();
        return;
    }

    int s0 = q * CHUNK;
    int s1 = (q == Q_ - 1) ? S_ : s0 + CHUNK;

    const float4* xb = x + (size_t)b * S_ * D4_ + t;
    float4* ob = ((float4*)(out + PE_OFF)) + (size_t)b * ROWS_PE * D4_ + (size_t)ROWS_TOK * D4_ + t;

    float4 acc = make_float4(0.f, 0.f, 0.f, 0.f);
    int s = s0;
    for (; s + 5 <= s1; s += 5) {
        float4 v0 = __ldcs(xb + (size_t)(s + 0) * D4_);
        float4 v1 = __ldcs(xb + (size_t)(s + 1) * D4_);
        float4 v2 = __ldcs(xb + (size_t)(s + 2) * D4_);
        float4 v3 = __ldcs(xb + (size_t)(s + 3) * D4_);
        float4 v4 = __ldcs(xb + (size_t)(s + 4) * D4_);
        acc.x += v0.x + v1.x + v2.x + v3.x + v4.x;
        acc.y += v0.y + v1.y + v2.y + v3.y + v4.y;
        acc.z += v0.z + v1.z + v2.z + v3.z + v4.z;
        acc.w += v0.w + v1.w + v2.w + v3.w + v4.w;
        __stcs(ob + (size_t)(s + 0) * D4_, v0);
        __stcs(ob + (size_t)(s + 1) * D4_, v1);
        __stcs(ob + (size_t)(s + 2) * D4_, v2);
        __stcs(ob + (size_t)(s + 3) * D4_, v3);
        __stcs(ob + (size_t)(s + 4) * D4_, v4);
    }
    for (; s < s1; s++) {
        float4 v = __ldcs(xb + (size_t)s * D4_);
        acc.x += v.x; acc.y += v.y; acc.z += v.z; acc.w += v.w;
        __stcs(ob + (size_t)s * D4_, v);
    }
    ((float4*)g_part)[(size_t)q * B_ * D4_ + (size_t)b * D4_ + t] = acc;
    cudaTriggerProgrammaticLaunchCompletion();
}

// ---------------------------------------------------------------------------
// Kernel 2: grid B, block 192. PDL secondary of k1.
// Triggers k3 launch IMMEDIATELY (its assist blocks have no dependency),
// then waits on k1, combines partials -> mean -> l2norm -> x_norm out;
// 20 similarity dots; top-5 / idx / counts.
// ---------------------------------------------------------------------------
__global__ void k_xnorm_topk(float* __restrict__ out) {
    __shared__ float  sh[256];
    __shared__ float4 shx[D4_];
    __shared__ float  shsim[P_];
    int b = blockIdx.x;
    int t = threadIdx.x;

    cudaTriggerProgrammaticLaunchCompletion();   // let k3's assist blocks start
    cudaGridDependencySynchronize();             // wait for k1's g_part/g_pnorm

    const float4* part = (const float4*)g_part + (size_t)b * D4_ + t;
    float4 a = make_float4(0.f, 0.f, 0.f, 0.f);
#pragma unroll
    for (int q = 0; q < Q_; q++) {
        float4 c = part[(size_t)q * B_ * D4_];
        a.x += c.x; a.y += c.y; a.z += c.z; a.w += c.w;
    }
    const float inv = 1.0f / (float)S_;
    a.x *= inv; a.y *= inv; a.z *= inv; a.w *= inv;

    sh[t] = a.x * a.x + a.y * a.y + a.z * a.z + a.w * a.w;
    if (t < 64) sh[192 + t] = 0.f;
    __syncthreads();
    for (int s = 128; s > 0; s >>= 1) {
        if (t < s) sh[t] += sh[t + s];
        __syncthreads();
    }
    float r = rsqrtf(fmaxf(sh[0], 1e-12f));
    float4 n = make_float4(a.x * r, a.y * r, a.z * r, a.w * r);

    ((float4*)g_xnorm)[(size_t)b * D4_ + t] = n;
    float* xo = out + XN_OFF + (size_t)b * D_ + (size_t)t * 4;
    xo[0] = n.x; xo[1] = n.y; xo[2] = n.z; xo[3] = n.w;

    shx[t] = n;
    __syncthreads();

    int w = t >> 5;          // 0..5
    int lane = t & 31;
    for (int p = w; p < P_; p += 6) {
        const float4* pn = ((const float4*)g_pnorm) + (size_t)p * D4_;
        float acc = 0.f;
#pragma unroll
        for (int i = 0; i < 6; i++) {
            int j = lane + 32 * i;
            float4 pv = pn[j];
            float4 xv = shx[j];
            acc += xv.x * pv.x + xv.y * pv.y + xv.z * pv.z + xv.w * pv.w;
        }
#pragma unroll
        for (int off = 16; off > 0; off >>= 1)
            acc += __shfl_down_sync(0xffffffffu, acc, off);
        if (lane == 0) shsim[p] = acc;
    }
    __syncthreads();

    if (t == 0) {
        float sim[P_];
        bool used[P_];
#pragma unroll
        for (int p = 0; p < P_; p++) { sim[p] = shsim[p]; used[p] = false; }
        for (int k = 0; k < K_; k++) {
            float best = -3.4e38f;
            int bi = 0;
#pragma unroll
            for (int p = 0; p < P_; p++) {
                if (!used[p] && sim[p] > best) { best = sim[p]; bi = p; }
            }
            used[bi] = true;
            bool keep = best > 0.0f;
            int idxp = keep ? bi : -1;
            g_idx[b * K_ + k] = idxp;
            out[IDX_OFF + (size_t)b * K_ + k] = (float)idxp;
            if (keep) atomicAdd(&g_cnt[bi], 1);
        }
    }
}

// ---------------------------------------------------------------------------
// Kernel 3: grid (76, B), block 192. PDL secondary of k2.
//  r<50        : assist row (NO dependency — runs concurrently with k2).
//  50<=r<75    : sync on k2, then selected-prompt row.
//  r==75, b<16 : sync on k2, reduce_sim partial, atomicAdd to SIM slot.
// All rows write prompted_embedding[:, r, :] AND tokens[:, r, :].
// ---------------------------------------------------------------------------
__global__ void k_tokens(const float4* __restrict__ prompt,
                         const float4* __restrict__ assist,
                         float* __restrict__ out) {
    int r = blockIdx.x;      // 0..75
    int b = blockIdx.y;
    int t = threadIdx.x;     // 0..191

    if (r == ROWS_TOK) {
        if (b >= RSB) return;
        cudaGridDependencySynchronize();
        const float4* xn = (const float4*)g_xnorm + (size_t)(b * 16) * D4_ + t;
        float4 sx = make_float4(0.f, 0.f, 0.f, 0.f);
#pragma unroll
        for (int i = 0; i < 16; i++) {
            float4 v = xn[(size_t)i * D4_];
            sx.x += v.x; sx.y += v.y; sx.z += v.z; sx.w += v.w;
        }
        float4 kt = make_float4(0.f, 0.f, 0.f, 0.f);
#pragma unroll
        for (int p = 0; p < P_; p++) {
            float c = (float)g_cnt[p];
            float4 v = ((const float4*)g_pnorm)[(size_t)p * D4_ + t];
            kt.x += c * v.x; kt.y += c * v.y; kt.z += c * v.z; kt.w += c * v.w;
        }
        float partial = sx.x * kt.x + sx.y * kt.y + sx.z * kt.z + sx.w * kt.w;
        float tot = blk_reduce_192(partial);
        if (t == 0) atomicAdd(out + SIM_OFF, tot * (1.0f / (float)B_));
        return;
    }

    float4 v;
    if (r < ROWS_ASSIST) {
        v = assist[(size_t)r * D4_ + t];
    } else {
        cudaGridDependencySynchronize();
        int rr = r - ROWS_ASSIST;
        int idx = g_idx[b * K_ + rr / L_];
        v = make_float4(0.f, 0.f, 0.f, 0.f);
        if (idx >= 0)
            v = prompt[((size_t)idx * L_ + (rr % L_)) * D4_ + t];
    }
    __stcs((float4*)(out + PE_OFF) + (size_t)b * ROWS_PE * D4_ + (size_t)r * D4_ + t, v);
    float* to = out + TOK_OFF + (size_t)b * ROWS_TOK * D_ + (size_t)t * 4 + (size_t)r * D_;
    __stcs(to + 0, v.x);
    __stcs(to + 1, v.y);
    __stcs(to + 2, v.z);
    __stcs(to + 3, v.w);
}

extern "C" void kernel_launch(void* const* d_in, const int* in_sizes, int n_in,
                              void* d_out, int out_size) {
    const float4* x_embed = (const float4*)d_in[0];        // [B,S,D]
    const float4* prompt = (const float4*)d_in[1];         // [P,L,D]
    const float4* prompt_key = (const float4*)d_in[2];     // [P,D]
    const float4* assist = (const float4*)d_in[3];         // [T,L,D]
    float* out = (float*)d_out;

    k_mean_copy<<<dim3(B_, Q_ + 1), D4_>>>(x_embed, prompt_key, out);

    cudaLaunchAttribute attr[1];
    attr[0].id = cudaLaunchAttributeProgrammaticStreamSerialization;
    attr[0].val.programmaticStreamSerializationAllowed = 1;

    {
        cudaLaunchConfig_t cfg = {};
        cfg.gridDim = dim3(B_, 1, 1);
        cfg.blockDim = dim3(D4_, 1, 1);
        cfg.stream = 0;
        cfg.attrs = attr;
        cfg.numAttrs = 1;
        cudaLaunchKernelEx(&cfg, k_xnorm_topk, out);
    }
    {
        cudaLaunchConfig_t cfg = {};
        cfg.gridDim = dim3(ROWS_TOK + 1, B_, 1);
        cfg.blockDim = dim3(D4_, 1, 1);
        cfg.stream = 0;
        cfg.attrs = attr;
        cfg.numAttrs = 1;
        cudaLaunchKernelEx(&cfg, k_tokens, prompt, assist, out);
    }
}

// round 10
// speedup vs baseline: 1.1923x; 1.0311x over previous
#include <cuda_runtime.h>

#define B_ 256
#define S_ 197
#define D_ 768
#define D4_ 192
#define P_ 20
#define L_ 5
#define T_ 10
#define K_ 5
#define ROWS_TOK 75            // (T+K)*L
#define ROWS_ASSIST 50         // T*L
#define ROWS_PE 272            // ROWS_TOK + S
#define Q_ 8                   // mean/copy chunks per batch row
#define CHUNK 25               // rows per chunk (last chunk = 22)
#define RSB 16                 // reduce_sim blocks (16 b's each)

// float offsets into d_out
#define PE_OFF   0ULL
#define SIM_OFF  53477376ULL
#define TOK_OFF  53477377ULL
#define IDX_OFF  68222977ULL
#define XN_OFF   68224257ULL

// scratch (device globals; no allocations)
__device__ float g_part[Q_ * B_ * D_];
__device__ float g_xnorm[B_ * D_];
__device__ float g_pnorm[P_ * D_];
__device__ int   g_idx[B_ * K_];
__device__ int   g_cnt[P_];

// 192-thread block reduce (padded to 256 in shared)
__device__ __forceinline__ float blk_reduce_192(float v) {
    __shared__ float sh[256];
    int t = threadIdx.x;
    sh[t] = v;
    if (t < 64) sh[192 + t] = 0.f;
    __syncthreads();
    for (int s = 128; s > 0; s >>= 1) {
        if (t < s) sh[t] += sh[t + s];
        __syncthreads();
    }
    return sh[0];
}

// Write one 768-float row (staged in shared, `srow`) to out at float offset g0,
// where g0 % 4 == 1. Emits 191 aligned float4 stores + 4 edge scalars.
__device__ __forceinline__ void store_row_aligned(float* __restrict__ out,
                                                  size_t g0,
                                                  const float* __restrict__ srow,
                                                  int t) {
    if (t < 191) {
        float4 w = make_float4(srow[3 + 4 * t], srow[4 + 4 * t],
                               srow[5 + 4 * t], srow[6 + 4 * t]);
        __stcs((float4*)(out + g0 + 3) + t, w);
    } else {
        __stcs(out + g0 + 0, srow[0]);
        __stcs(out + g0 + 1, srow[1]);
        __stcs(out + g0 + 2, srow[2]);
        __stcs(out + g0 + 767, srow[767]);
    }
}

// ---------------------------------------------------------------------------
// Kernel 1: grid (B, Q_+1), block 192.
//  q<Q_ : stream x_embed rows chunk -> prompted_embedding[:, 75:, :] + partials.
//  q==Q_: b<P -> l2-normalize prompt_key row b; b==0 zeroes g_cnt + SIM slot.
// ---------------------------------------------------------------------------
__global__ void k_mean_copy(const float4* __restrict__ x,
                            const float4* __restrict__ pk,
                            float* __restrict__ out) {
    int b = blockIdx.x;
    int q = blockIdx.y;
    int t = threadIdx.x;                 // 0..191

    if (q == Q_) {
        if (b == 0 && t < P_) g_cnt[t] = 0;
        if (b == 0 && t == 0) out[SIM_OFF] = 0.f;
        if (b < P_) {
            float4 v = pk[(size_t)b * D4_ + t];
            float ss = blk_reduce_192(v.x * v.x + v.y * v.y + v.z * v.z + v.w * v.w);
            float r = rsqrtf(fmaxf(ss, 1e-12f));
            float4 n = make_float4(v.x * r, v.y * r, v.z * r, v.w * r);
            ((float4*)g_pnorm)[(size_t)b * D4_ + t] = n;
        }
        cudaTriggerProgrammaticLaunchCompletion();
        return;
    }

    int s0 = q * CHUNK;
    int s1 = (q == Q_ - 1) ? S_ : s0 + CHUNK;

    const float4* xb = x + (size_t)b * S_ * D4_ + t;
    float4* ob = ((float4*)(out + PE_OFF)) + (size_t)b * ROWS_PE * D4_ + (size_t)ROWS_TOK * D4_ + t;

    float4 acc = make_float4(0.f, 0.f, 0.f, 0.f);
    int s = s0;
    for (; s + 5 <= s1; s += 5) {
        float4 v0 = __ldcs(xb + (size_t)(s + 0) * D4_);
        float4 v1 = __ldcs(xb + (size_t)(s + 1) * D4_);
        float4 v2 = __ldcs(xb + (size_t)(s + 2) * D4_);
        float4 v3 = __ldcs(xb + (size_t)(s + 3) * D4_);
        float4 v4 = __ldcs(xb + (size_t)(s + 4) * D4_);
        acc.x += v0.x + v1.x + v2.x + v3.x + v4.x;
        acc.y += v0.y + v1.y + v2.y + v3.y + v4.y;
        acc.z += v0.z + v1.z + v2.z + v3.z + v4.z;
        acc.w += v0.w + v1.w + v2.w + v3.w + v4.w;
        __stcs(ob + (size_t)(s + 0) * D4_, v0);
        __stcs(ob + (size_t)(s + 1) * D4_, v1);
        __stcs(ob + (size_t)(s + 2) * D4_, v2);
        __stcs(ob + (size_t)(s + 3) * D4_, v3);
        __stcs(ob + (size_t)(s + 4) * D4_, v4);
    }
    for (; s < s1; s++) {
        float4 v = __ldcs(xb + (size_t)s * D4_);
        acc.x += v.x; acc.y += v.y; acc.z += v.z; acc.w += v.w;
        __stcs(ob + (size_t)s * D4_, v);
    }
    ((float4*)g_part)[(size_t)q * B_ * D4_ + (size_t)b * D4_ + t] = acc;
    cudaTriggerProgrammaticLaunchCompletion();
}

// ---------------------------------------------------------------------------
// Kernel 2: grid B, block 192. PDL secondary of k1.
// Triggers k3 launch immediately, waits on k1, combines partials -> mean ->
// l2norm -> x_norm out (aligned); 20 similarity dots; top-5 / idx / counts.
// ---------------------------------------------------------------------------
__global__ void k_xnorm_topk(float* __restrict__ out) {
    __shared__ float  sh[256];
    __shared__ float4 shx[D4_];
    __shared__ float  shsim[P_];
    int b = blockIdx.x;
    int t = threadIdx.x;

    cudaTriggerProgrammaticLaunchCompletion();   // let k3's assist blocks start
    cudaGridDependencySynchronize();             // wait for k1's g_part/g_pnorm

    const float4* part = (const float4*)g_part + (size_t)b * D4_ + t;
    float4 a = make_float4(0.f, 0.f, 0.f, 0.f);
#pragma unroll
    for (int q = 0; q < Q_; q++) {
        float4 c = part[(size_t)q * B_ * D4_];
        a.x += c.x; a.y += c.y; a.z += c.z; a.w += c.w;
    }
    const float inv = 1.0f / (float)S_;
    a.x *= inv; a.y *= inv; a.z *= inv; a.w *= inv;

    sh[t] = a.x * a.x + a.y * a.y + a.z * a.z + a.w * a.w;
    if (t < 64) sh[192 + t] = 0.f;
    __syncthreads();
    for (int s = 128; s > 0; s >>= 1) {
        if (t < s) sh[t] += sh[t + s];
        __syncthreads();
    }
    float r = rsqrtf(fmaxf(sh[0], 1e-12f));
    float4 n = make_float4(a.x * r, a.y * r, a.z * r, a.w * r);

    ((float4*)g_xnorm)[(size_t)b * D4_ + t] = n;

    shx[t] = n;
    __syncthreads();

    // x_norm output (row start ≡ 1 mod 4) — aligned stores from shared
    store_row_aligned(out, XN_OFF + (size_t)b * D_, (const float*)shx, t);

    int w = t >> 5;          // 0..5
    int lane = t & 31;
    for (int p = w; p < P_; p += 6) {
        const float4* pn = ((const float4*)g_pnorm) + (size_t)p * D4_;
        float acc = 0.f;
#pragma unroll
        for (int i = 0; i < 6; i++) {
            int j = lane + 32 * i;
            float4 pv = pn[j];
            float4 xv = shx[j];
            acc += xv.x * pv.x + xv.y * pv.y + xv.z * pv.z + xv.w * pv.w;
        }
#pragma unroll
        for (int off = 16; off > 0; off >>= 1)
            acc += __shfl_down_sync(0xffffffffu, acc, off);
        if (lane == 0) shsim[p] = acc;
    }
    __syncthreads();

    if (t == 0) {
        float sim[P_];
        bool used[P_];
#pragma unroll
        for (int p = 0; p < P_; p++) { sim[p] = shsim[p]; used[p] = false; }
        for (int k = 0; k < K_; k++) {
            float best = -3.4e38f;
            int bi = 0;
#pragma unroll
            for (int p = 0; p < P_; p++) {
                if (!used[p] && sim[p] > best) { best = sim[p]; bi = p; }
            }
            used[bi] = true;
            bool keep = best > 0.0f;
            int idxp = keep ? bi : -1;
            g_idx[b * K_ + k] = idxp;
            out[IDX_OFF + (size_t)b * K_ + k] = (float)idxp;
            if (keep) atomicAdd(&g_cnt[bi], 1);
        }
    }
}

// ---------------------------------------------------------------------------
// Kernel 3: grid (76, B), block 192. PDL secondary of k2.
//  r<50        : assist row (NO dependency — runs concurrently with k2).
//  50<=r<75    : sync on k2, then selected-prompt row.
//  r==75, b<16 : sync on k2, reduce_sim partial, atomicAdd to SIM slot.
// PE write is float4-aligned; TOK write realigned via shared staging.
// ---------------------------------------------------------------------------
__global__ void k_tokens(const float4* __restrict__ prompt,
                         const float4* __restrict__ assist,
                         float* __restrict__ out) {
    __shared__ float srow[D_];
    int r = blockIdx.x;      // 0..75
    int b = blockIdx.y;
    int t = threadIdx.x;     // 0..191

    if (r == ROWS_TOK) {
        if (b >= RSB) return;
        cudaGridDependencySynchronize();
        const float4* xn = (const float4*)g_xnorm + (size_t)(b * 16) * D4_ + t;
        float4 sx = make_float4(0.f, 0.f, 0.f, 0.f);
#pragma unroll
        for (int i = 0; i < 16; i++) {
            float4 v = xn[(size_t)i * D4_];
            sx.x += v.x; sx.y += v.y; sx.z += v.z; sx.w += v.w;
        }
        float4 kt = make_float4(0.f, 0.f, 0.f, 0.f);
#pragma unroll
        for (int p = 0; p < P_; p++) {
            float c = (float)g_cnt[p];
            float4 v = ((const float4*)g_pnorm)[(size_t)p * D4_ + t];
            kt.x += c * v.x; kt.y += c * v.y; kt.z += c * v.z; kt.w += c * v.w;
        }
        float partial = sx.x * kt.x + sx.y * kt.y + sx.z * kt.z + sx.w * kt.w;
        float tot = blk_reduce_192(partial);
        if (t == 0) atomicAdd(out + SIM_OFF, tot * (1.0f / (float)B_));
        return;
    }

    float4 v;
    if (r < ROWS_ASSIST) {
        v = assist[(size_t)r * D4_ + t];
    } else {
        cudaGridDependencySynchronize();
        int rr = r - ROWS_ASSIST;
        int idx = g_idx[b * K_ + rr / L_];
        v = make_float4(0.f, 0.f, 0.f, 0.f);
        if (idx >= 0)
            v = prompt[((size_t)idx * L_ + (rr % L_)) * D4_ + t];
    }
    __stcs((float4*)(out + PE_OFF) + (size_t)b * ROWS_PE * D4_ + (size_t)r * D4_ + t, v);

    // tokens write: realign through shared (row start ≡ 1 mod 4)
    *(float4*)&srow[4 * t] = v;
    __syncthreads();
    store_row_aligned(out, TOK_OFF + (size_t)b * ROWS_TOK * D_ + (size_t)r * D_, srow, t);
}

extern "C" void kernel_launch(void* const* d_in, const int* in_sizes, int n_in,
                              void* d_out, int out_size) {
    const float4* x_embed = (const float4*)d_in[0];        // [B,S,D]
    const float4* prompt = (const float4*)d_in[1];         // [P,L,D]
    const float4* prompt_key = (const float4*)d_in[2];     // [P,D]
    const float4* assist = (const float4*)d_in[3];         // [T,L,D]
    float* out = (float*)d_out;

    k_mean_copy<<<dim3(B_, Q_ + 1), D4_>>>(x_embed, prompt_key, out);

    cudaLaunchAttribute attr[1];
    attr[0].id = cudaLaunchAttributeProgrammaticStreamSerialization;
    attr[0].val.programmaticStreamSerializationAllowed = 1;

    {
        cudaLaunchConfig_t cfg = {};
        cfg.gridDim = dim3(B_, 1, 1);
        cfg.blockDim = dim3(D4_, 1, 1);
        cfg.stream = 0;
        cfg.attrs = attr;
        cfg.numAttrs = 1;
        cudaLaunchKernelEx(&cfg, k_xnorm_topk, out);
    }
    {
        cudaLaunchConfig_t cfg = {};
        cfg.gridDim = dim3(ROWS_TOK + 1, B_, 1);
        cfg.blockDim = dim3(D4_, 1, 1);
        cfg.stream = 0;
        cfg.attrs = attr;
        cfg.numAttrs = 1;
        cudaLaunchKernelEx(&cfg, k_tokens, prompt, assist, out);
    }
}